// round 15
// baseline (speedup 1.0000x reference)
#include <cuda_runtime.h>
#include <math_constants.h>

#define WIN   400
#define RNUM  64
#define BNUM  2
#define ANUM  3
#define KSEL  8
#define WPC   2                 // windows per CTA
#define SPAN  (WIN * WPC)       // 800 floats
#define NV4S  (SPAN / 4)        // 200 float4 per row span
#define NTHR  128
#define NWARP (NTHR / 32)       // 4
#define RPW   (RNUM / NWARP)    // 16 rows per warp

__global__ __launch_bounds__(NTHR, 11) void win_topk_kernel(
    const float* __restrict__ mixed,    // [B, S]
    const float* __restrict__ ref,      // [A, R, S]
    const float* __restrict__ weights,  // [K]
    float* __restrict__ out,            // [6*W] scores ++ [6*W*K] idx (as float)
    int S, int W, int write_idx)
{
    const int wg   = blockIdx.x;        // window-pair index
    const int a    = blockIdx.y;
    const int tid  = threadIdx.x;
    const int warp = tid >> 5;
    const int lane = tid & 31;

    __shared__ __align__(16) float sm_mixed[BNUM][SPAN];
    __shared__ float sm_scores[BNUM][WPC][RNUM];
    __shared__ float sm_w[KSEL];

    const long base = (long)wg * SPAN;

    // Stage mixed span (both batch rows) into shared, vectorized.
    {
        const float4* m4 = (const float4*)mixed;  // S % 4 == 0, base % 4 == 0
        float4* sm4 = (float4*)&sm_mixed[0][0];
        for (int i = tid; i < BNUM * NV4S; i += NTHR) {   // 400 float4
            int b = i / NV4S, v = i % NV4S;
            sm4[i] = m4[((long)b * S + base) / 4 + v];
        }
        if (tid < KSEL) sm_w[tid] = weights[tid];
    }
    __syncthreads();

    // Each warp streams 16 ref rows, processed in PAIRS: two independent
    // 3.2KB load streams in flight, shared mixed operands, grouped reductions.
    {
        const float4* sm0 = (const float4*)&sm_mixed[0][0];
        const float4* sm1 = (const float4*)&sm_mixed[1][0];
        const float* refa = ref + ((long)a * RNUM) * S + base;

        for (int ii = 0; ii < RPW; ii += 2) {
            const int r0 = warp * RPW + ii;
            const float4* rowA = (const float4*)(refa + (long)r0 * S);
            const float4* rowB = (const float4*)(refa + (long)(r0 + 1) * S);

            float a00 = 0.f, a01 = 0.f, a10 = 0.f, a11 = 0.f;  // row r0
            float b00 = 0.f, b01 = 0.f, b10 = 0.f, b11 = 0.f;  // row r0+1

            #pragma unroll
            for (int j = 0; j < 6; j++) {   // 192 vec4 full-warp
                int v = lane + j * 32;
                float4 rA = __ldcs(&rowA[v]);
                float4 rB = __ldcs(&rowB[v]);
                float4 m0 = sm0[v];
                float4 m1 = sm1[v];
                float cA0 = rA.x * m0.x;
                cA0 = fmaf(rA.y, m0.y, cA0);
                cA0 = fmaf(rA.z, m0.z, cA0);
                cA0 = fmaf(rA.w, m0.w, cA0);
                float cA1 = rA.x * m1.x;
                cA1 = fmaf(rA.y, m1.y, cA1);
                cA1 = fmaf(rA.z, m1.z, cA1);
                cA1 = fmaf(rA.w, m1.w, cA1);
                float cB0 = rB.x * m0.x;
                cB0 = fmaf(rB.y, m0.y, cB0);
                cB0 = fmaf(rB.z, m0.z, cB0);
                cB0 = fmaf(rB.w, m0.w, cB0);
                float cB1 = rB.x * m1.x;
                cB1 = fmaf(rB.y, m1.y, cB1);
                cB1 = fmaf(rB.z, m1.z, cB1);
                cB1 = fmaf(rB.w, m1.w, cB1);
                if (v < WIN / 4) { a00 += cA0; a10 += cA1; b00 += cB0; b10 += cB1; }
                else             { a01 += cA0; a11 += cA1; b01 += cB0; b11 += cB1; }
            }
            if (lane < NV4S - 192) {        // tail: vec4 192..199 (all win1)
                int v = 192 + lane;
                float4 rA = __ldcs(&rowA[v]);
                float4 rB = __ldcs(&rowB[v]);
                float4 m0 = sm0[v];
                float4 m1 = sm1[v];
                float cA0 = rA.x * m0.x;
                cA0 = fmaf(rA.y, m0.y, cA0);
                cA0 = fmaf(rA.z, m0.z, cA0);
                cA0 = fmaf(rA.w, m0.w, cA0);
                float cA1 = rA.x * m1.x;
                cA1 = fmaf(rA.y, m1.y, cA1);
                cA1 = fmaf(rA.z, m1.z, cA1);
                cA1 = fmaf(rA.w, m1.w, cA1);
                float cB0 = rB.x * m0.x;
                cB0 = fmaf(rB.y, m0.y, cB0);
                cB0 = fmaf(rB.z, m0.z, cB0);
                cB0 = fmaf(rB.w, m0.w, cB0);
                float cB1 = rB.x * m1.x;
                cB1 = fmaf(rB.y, m1.y, cB1);
                cB1 = fmaf(rB.z, m1.z, cB1);
                cB1 = fmaf(rB.w, m1.w, cB1);
                a01 += cA0; a11 += cA1; b01 += cB0; b11 += cB1;
            }
            // Grouped warp reductions (8 values)
            #pragma unroll
            for (int off = 16; off > 0; off >>= 1) {
                a00 += __shfl_down_sync(0xffffffffu, a00, off);
                a01 += __shfl_down_sync(0xffffffffu, a01, off);
                a10 += __shfl_down_sync(0xffffffffu, a10, off);
                a11 += __shfl_down_sync(0xffffffffu, a11, off);
                b00 += __shfl_down_sync(0xffffffffu, b00, off);
                b01 += __shfl_down_sync(0xffffffffu, b01, off);
                b10 += __shfl_down_sync(0xffffffffu, b10, off);
                b11 += __shfl_down_sync(0xffffffffu, b11, off);
            }
            if (lane == 0) {
                sm_scores[0][0][r0]     = a00 * (1.0f / WIN);
                sm_scores[0][1][r0]     = a01 * (1.0f / WIN);
                sm_scores[1][0][r0]     = a10 * (1.0f / WIN);
                sm_scores[1][1][r0]     = a11 * (1.0f / WIN);
                sm_scores[0][0][r0 + 1] = b00 * (1.0f / WIN);
                sm_scores[0][1][r0 + 1] = b01 * (1.0f / WIN);
                sm_scores[1][0][r0 + 1] = b10 * (1.0f / WIN);
                sm_scores[1][1][r0 + 1] = b11 * (1.0f / WIN);
            }
        }
    }
    __syncthreads();

    // Top-K (K=8) over 64 refs; warps 0..3 handle the 4 (b, win) combos.
    {
        const int b   = warp >> 1;
        const int win = warp & 1;
        float v0 = sm_scores[b][win][lane];
        float v1 = sm_scores[b][win][lane + 32];
        float acc = 0.f;

        const int  wglob = wg * WPC + win;
        const long ow    = ((long)b * ANUM + a) * W + wglob;
        const long ibase = (long)BNUM * ANUM * W + ow * KSEL;

        #pragma unroll
        for (int k = 0; k < KSEL; k++) {
            float bv; int bi;
            if (v0 >= v1) { bv = v0; bi = lane; }        // ties -> lower index
            else          { bv = v1; bi = lane + 32; }
            #pragma unroll
            for (int off = 16; off > 0; off >>= 1) {
                float ov = __shfl_xor_sync(0xffffffffu, bv, off);
                int   oi = __shfl_xor_sync(0xffffffffu, bi, off);
                if (ov > bv || (ov == bv && oi < bi)) { bv = ov; bi = oi; }
            }
            acc = fmaf(bv, sm_w[k], acc);
            if (write_idx && lane == 0) out[ibase + k] = (float)bi;
            if (bi == lane)      v0 = -CUDART_INF_F;
            if (bi == lane + 32) v1 = -CUDART_INF_F;
        }
        if (lane == 0) out[ow] = acc;
    }
}

extern "C" void kernel_launch(void* const* d_in, const int* in_sizes, int n_in,
                              void* d_out, int out_size) {
    const float* mixed   = (const float*)d_in[0];
    const float* ref     = (const float*)d_in[1];
    const float* weights = (const float*)d_in[2];
    float* out = (float*)d_out;

    const int S = in_sizes[0] / BNUM;      // 400000
    const int W = S / WIN;                 // 1000
    const int write_idx = (out_size >= BNUM * ANUM * W * (1 + KSEL)) ? 1 : 0;

    dim3 grid(W / WPC, ANUM);              // (500, 3) = 1500 CTAs x 128 thr
    win_topk_kernel<<<grid, NTHR>>>(mixed, ref, weights, out, S, W, write_idx);
}